// round 1
// baseline (speedup 1.0000x reference)
#include <cuda_runtime.h>
#include <math.h>

#define T_LEN 8192
#define NDELAY 360
#define MIN_DELAY_C 60
#define NTHREADS 512

// Scalar recurrence parameters computed by setup kernel.
__device__ float g_a1, g_a2;
__device__ int   g_L1, g_L2, g_C;

// ---------------------------------------------------------------------------
// Setup: argmax over 360 logits (first-index tie-break, matching jnp.argmax),
// then closed-form a1/a2 from reflection coeffs + feedback gain.
// The straight-through one-hot is exactly hard in fp32 for the zero entries
// ((0 - s) + s == 0 in IEEE), so the 420-tap filter has exactly two taps.
// ---------------------------------------------------------------------------
__global__ void ks_setup_kernel(const float* __restrict__ gumbel,
                                const float* __restrict__ delay_param,
                                const float* __restrict__ feedback_gain,
                                const float* __restrict__ refl) {
    __shared__ float svals[NTHREADS];
    __shared__ int   sidx[NTHREADS];
    int tid = threadIdx.x;

    float v = -INFINITY;
    int   idx = 0;
    if (tid < NDELAY) {
        v = delay_param[tid] + gumbel[tid];
        idx = tid;
    }
    svals[tid] = v;
    sidx[tid]  = idx;
    __syncthreads();

    for (int off = NTHREADS / 2; off > 0; off >>= 1) {
        if (tid < off) {
            float v2 = svals[tid + off];
            int   i2 = sidx[tid + off];
            if (v2 > svals[tid] || (v2 == svals[tid] && i2 < sidx[tid])) {
                svals[tid] = v2;
                sidx[tid]  = i2;
            }
        }
        __syncthreads();
    }

    if (tid == 0) {
        int m = sidx[0];
        // k = resonant_activation(tanh(c), tau=0) == tanh(tanh(c))
        float k1 = tanhf(tanhf(refl[0]));
        float k2 = tanhf(tanhf(refl[1]));
        float a1 = k1 * (1.0f - k2);
        float a2 = fminf(fmaxf(k2, -0.999f), 0.999f);
        float bound = 0.999f - fabsf(a2);
        a1 = fminf(fmaxf(a1, -bound), bound);
        float g = powf(1.0f / (1.0f + expf(-feedback_gain[0])), 0.45f);
        a1 *= g;
        a2 *= g;

        int L1 = MIN_DELAY_C + 1 + m;                       // tap from one_hot
        int L2 = MIN_DELAY_C + 1 + ((m + 1) % NDELAY);      // tap from roll(one_hot,1)
        g_a1 = a1;
        g_a2 = a2;
        g_L1 = L1;
        g_L2 = L2;
        g_C  = (L1 < L2) ? L1 : L2;   // chunk width: both taps look >= C behind
    }
}

// ---------------------------------------------------------------------------
// Main: one CTA per batch row. Stage the whole row in SMEM, run the 2-tap
// recurrence in place in chunks of C samples (all independent within a chunk
// since both lags >= C), write back coalesced.
// ---------------------------------------------------------------------------
__global__ void __launch_bounds__(NTHREADS)
ks_resonator_kernel(const float* __restrict__ x, float* __restrict__ out) {
    __shared__ float buf[T_LEN];
    const int row = blockIdx.x;
    const int tid = threadIdx.x;
    const float* xr = x + (size_t)row * T_LEN;
    float*       yr = out + (size_t)row * T_LEN;

    // Stage excitation row into SMEM (coalesced, MLP=16).
#pragma unroll
    for (int i = 0; i < T_LEN / NTHREADS; i++)
        buf[tid + i * NTHREADS] = xr[tid + i * NTHREADS];

    const float a1 = g_a1;
    const float a2 = g_a2;
    const int   L1 = g_L1;
    const int   L2 = g_L2;
    const int   C  = g_C;
    __syncthreads();

    // Sequential chunk chain: y_t = x_t - a1*y_{t-L1} - a2*y_{t-L2}
    for (int s = 0; s < T_LEN; s += C) {
        int t = s + tid;
        if (tid < C && t < T_LEN) {
            float v  = buf[t];
            float y1 = (t >= L1) ? buf[t - L1] : 0.0f;
            float y2 = (t >= L2) ? buf[t - L2] : 0.0f;
            buf[t] = v - (a1 * y1 + a2 * y2);
        }
        __syncthreads();
    }

    // Write back coalesced.
#pragma unroll
    for (int i = 0; i < T_LEN / NTHREADS; i++)
        yr[tid + i * NTHREADS] = buf[tid + i * NTHREADS];
}

// ---------------------------------------------------------------------------
// inputs (metadata order): excitation[128*1*8192] f32, gumbel_noise[360] f32,
// delay_param[360] f32, feedback_gain[1] f32, reflection_coeffs[2] f32
// output: f32 [128*1*8192]
// ---------------------------------------------------------------------------
extern "C" void kernel_launch(void* const* d_in, const int* in_sizes, int n_in,
                              void* d_out, int out_size) {
    const float* x      = (const float*)d_in[0];
    const float* gumbel = (const float*)d_in[1];
    const float* delayp = (const float*)d_in[2];
    const float* fb     = (const float*)d_in[3];
    const float* rc     = (const float*)d_in[4];
    float* out = (float*)d_out;

    int rows = in_sizes[0] / T_LEN;

    ks_setup_kernel<<<1, NTHREADS>>>(gumbel, delayp, fb, rc);
    ks_resonator_kernel<<<rows, NTHREADS>>>(x, out);
}